// round 3
// baseline (speedup 1.0000x reference)
#include <cuda_runtime.h>
#include <math.h>

// ---------------------------------------------------------------------------
// AttentionBlock: B=16, C=512, H=W=32 (HW=1024), GROUPS=32
//   xn   = GroupNorm(x)                        [B, C, HW]
//   qkv  = qkv_w @ xn + qkv_b                  [B, 3C, HW]
//   S    = softmax(q^T k / sqrt(C))            [B, HW, HW]
//   h    = v @ S^T                             [B, C, HW]
//   out  = proj_w @ h + proj_b + x             [B, C, HW]
// ---------------------------------------------------------------------------

#define BATCH 16
#define C_DIM 512
#define HW    1024
#define GROUPS 32
#define CPG   (C_DIM / GROUPS)        // 16
#define GROUP_ELEMS (CPG * HW)        // 16384

// scratch (static device arrays; allocations are forbidden)
__device__ float g_xn  [BATCH * C_DIM * HW];        // 33.5 MB
__device__ float g_qkv [BATCH * 3 * C_DIM * HW];    // 100.7 MB
__device__ float g_attn[BATCH * HW * HW];           // 67 MB
__device__ float g_h   [BATCH * C_DIM * HW];        // 33.5 MB

// ---------------------------------------------------------------------------
// GroupNorm: one block per (b, g). Group region is contiguous (16 ch x 1024).
// ---------------------------------------------------------------------------
__global__ __launch_bounds__(256) void groupnorm_kernel(
    const float* __restrict__ x, const float* __restrict__ w,
    const float* __restrict__ b, float* __restrict__ out)
{
    const int bg = blockIdx.x;                  // b*32 + g
    const int g  = bg & (GROUPS - 1);
    const float* xp = x   + (long)bg * GROUP_ELEMS;
    float*       op = out + (long)bg * GROUP_ELEMS;
    const int tid = threadIdx.x;

    float s = 0.f, ss = 0.f;
    for (int i = tid; i < GROUP_ELEMS; i += 256) {
        float v = xp[i];
        s += v; ss += v * v;
    }
    __shared__ float red0[256], red1[256];
    red0[tid] = s; red1[tid] = ss;
    __syncthreads();
    for (int st = 128; st > 0; st >>= 1) {
        if (tid < st) { red0[tid] += red0[tid + st]; red1[tid] += red1[tid + st]; }
        __syncthreads();
    }
    const float mean = red0[0] * (1.0f / GROUP_ELEMS);
    const float var  = red1[0] * (1.0f / GROUP_ELEMS) - mean * mean;
    const float inv  = rsqrtf(var + 1e-5f);

    for (int i = tid; i < GROUP_ELEMS; i += 256) {
        int c = g * CPG + (i >> 10);            // i / HW
        op[i] = (xp[i] - mean) * inv * w[c] + b[c];
    }
}

// ---------------------------------------------------------------------------
// Generic strided batched SGEMM:
//   C[bz][i, j] = alpha * sum_k A[bz][i*sAi + k*sAk] * B[bz][k*sBk + j*sBj]
//                 (+ bias[i]) (+ res[bz][i, j])
// Tile 64x64x16, 256 threads, 4x4 micro-tile. All shapes divide tiles exactly.
// ---------------------------------------------------------------------------
#define BM 64
#define BN 64
#define BK 16
#define SPAD 4

template<bool ADD_BIAS, bool ADD_RES>
__global__ __launch_bounds__(256) void gemm_kernel(
    const float* __restrict__ A, const float* __restrict__ B_,
    float* __restrict__ C,
    int M, int N, int K,
    int sAi, int sAk, int sBk, int sBj,
    long bsA, long bsB, long bsC,
    float alpha,
    const float* __restrict__ bias,
    const float* __restrict__ res, long bsR)
{
    __shared__ float As[BK][BM + SPAD];
    __shared__ float Bs[BK][BN + SPAD];

    const int bz = blockIdx.z;
    const float* Ab = A  + bz * bsA;
    const float* Bb = B_ + bz * bsB;
    const int i0 = blockIdx.y * BM;
    const int j0 = blockIdx.x * BN;

    const int tid = threadIdx.x;
    const int tx = tid & 15;
    const int ty = tid >> 4;

    const bool aKfast = (sAk == 1);
    const bool bJfast = (sBj == 1);

    float acc[4][4] = {};

    for (int k0 = 0; k0 < K; k0 += BK) {
        // load A tile: iterate with the unit-stride axis fastest (coalesced)
        if (aKfast) {
            #pragma unroll
            for (int r = 0; r < 4; r++) {
                int t = tid + r * 256;
                int i = t >> 4, k = t & 15;
                As[k][i] = Ab[(long)(i0 + i) * sAi + (k0 + k)];
            }
        } else {
            #pragma unroll
            for (int r = 0; r < 4; r++) {
                int t = tid + r * 256;
                int i = t & 63, k = t >> 6;
                As[k][i] = Ab[(long)(i0 + i) * sAi + (long)(k0 + k) * sAk];
            }
        }
        // load B tile
        if (bJfast) {
            #pragma unroll
            for (int r = 0; r < 4; r++) {
                int t = tid + r * 256;
                int k = t >> 6, j = t & 63;
                Bs[k][j] = Bb[(long)(k0 + k) * sBk + (j0 + j)];
            }
        } else {
            #pragma unroll
            for (int r = 0; r < 4; r++) {
                int t = tid + r * 256;
                int j = t >> 4, k = t & 15;
                Bs[k][j] = Bb[(long)(k0 + k) * sBk + (long)(j0 + j) * sBj];
            }
        }
        __syncthreads();

        #pragma unroll
        for (int kk = 0; kk < BK; kk++) {
            float4 av = *(const float4*)&As[kk][ty * 4];
            float4 bv = *(const float4*)&Bs[kk][tx * 4];
            float a[4] = {av.x, av.y, av.z, av.w};
            float b[4] = {bv.x, bv.y, bv.z, bv.w};
            #pragma unroll
            for (int r = 0; r < 4; r++)
                #pragma unroll
                for (int c = 0; c < 4; c++)
                    acc[r][c] += a[r] * b[c];
        }
        __syncthreads();
    }

    float* Cb = C + bz * bsC;
    const float* Rb = ADD_RES ? (res + bz * bsR) : nullptr;

    #pragma unroll
    for (int r = 0; r < 4; r++) {
        const int i = i0 + ty * 4 + r;
        const float bv = ADD_BIAS ? bias[i] : 0.f;
        const long off = (long)i * N + j0 + tx * 4;
        float4 v;
        v.x = acc[r][0] * alpha + bv;
        v.y = acc[r][1] * alpha + bv;
        v.z = acc[r][2] * alpha + bv;
        v.w = acc[r][3] * alpha + bv;
        if (ADD_RES) {
            float4 rv = *(const float4*)&Rb[off];
            v.x += rv.x; v.y += rv.y; v.z += rv.z; v.w += rv.w;
        }
        *(float4*)&Cb[off] = v;
    }
}

// ---------------------------------------------------------------------------
// Row softmax over 1024 elements. One block (256 threads, float4 each) per row.
// ---------------------------------------------------------------------------
__global__ __launch_bounds__(256) void softmax_kernel(float* __restrict__ S)
{
    float* row = S + (long)blockIdx.x * HW;
    const int tid = threadIdx.x;
    float4 v = ((float4*)row)[tid];

    __shared__ float red[256];
    float m = fmaxf(fmaxf(v.x, v.y), fmaxf(v.z, v.w));
    red[tid] = m;
    __syncthreads();
    for (int st = 128; st > 0; st >>= 1) {
        if (tid < st) red[tid] = fmaxf(red[tid], red[tid + st]);
        __syncthreads();
    }
    m = red[0];
    __syncthreads();

    v.x = __expf(v.x - m); v.y = __expf(v.y - m);
    v.z = __expf(v.z - m); v.w = __expf(v.w - m);
    float s = v.x + v.y + v.z + v.w;
    red[tid] = s;
    __syncthreads();
    for (int st = 128; st > 0; st >>= 1) {
        if (tid < st) red[tid] += red[tid + st];
        __syncthreads();
    }
    const float inv = 1.0f / red[0];
    v.x *= inv; v.y *= inv; v.z *= inv; v.w *= inv;
    ((float4*)row)[tid] = v;
}

// ---------------------------------------------------------------------------
extern "C" void kernel_launch(void* const* d_in, const int* in_sizes, int n_in,
                              void* d_out, int out_size)
{
    const float* x      = (const float*)d_in[0];
    const float* norm_w = (const float*)d_in[1];
    const float* norm_b = (const float*)d_in[2];
    const float* qkv_w  = (const float*)d_in[3];
    const float* qkv_b  = (const float*)d_in[4];
    const float* proj_w = (const float*)d_in[5];
    const float* proj_b = (const float*)d_in[6];
    float* out = (float*)d_out;

    float *xn, *qkv, *attn, *h;
    cudaGetSymbolAddress((void**)&xn,   g_xn);
    cudaGetSymbolAddress((void**)&qkv,  g_qkv);
    cudaGetSymbolAddress((void**)&attn, g_attn);
    cudaGetSymbolAddress((void**)&h,    g_h);

    const long nCHW  = (long)C_DIM * HW;       // 512*1024
    const long n3CHW = 3 * nCHW;               // 1536*1024
    const long nSS   = (long)HW * HW;          // 1024*1024
    const float scale = 0.04419417382415922f;  // 1/sqrt(512)

    // 1) GroupNorm
    groupnorm_kernel<<<BATCH * GROUPS, 256>>>(x, norm_w, norm_b, xn);

    // 2) qkv[b] = qkv_w @ xn[b] + qkv_b   (M=1536, N=1024, K=512)
    gemm_kernel<true, false><<<dim3(HW / BN, 3 * C_DIM / BM, BATCH), 256>>>(
        qkv_w, xn, qkv, 3 * C_DIM, HW, C_DIM,
        /*sAi*/ C_DIM, /*sAk*/ 1, /*sBk*/ HW, /*sBj*/ 1,
        0, nCHW, n3CHW, 1.0f, qkv_b, nullptr, 0);

    // 3) S[b][n,m] = (1/sqrt(C)) * sum_c q[b][c,n] * k[b][c,m]   (M=N=1024, K=512)
    gemm_kernel<false, false><<<dim3(HW / BN, HW / BM, BATCH), 256>>>(
        qkv /*q*/, qkv + nCHW /*k*/, attn, HW, HW, C_DIM,
        /*sAi*/ 1, /*sAk*/ HW, /*sBk*/ HW, /*sBj*/ 1,
        n3CHW, n3CHW, nSS, scale, nullptr, nullptr, 0);

    // 4) softmax over last dim
    softmax_kernel<<<BATCH * HW, 256>>>(attn);

    // 5) h[b][c,n] = sum_m v[b][c,m] * S[b][n,m]   (M=512, N=1024, K=1024)
    gemm_kernel<false, false><<<dim3(HW / BN, C_DIM / BM, BATCH), 256>>>(
        qkv + 2 * nCHW /*v*/, attn, h, C_DIM, HW, HW,
        /*sAi*/ HW, /*sAk*/ 1, /*sBk*/ 1, /*sBj*/ HW,
        n3CHW, nSS, nCHW, 1.0f, nullptr, nullptr, 0);

    // 6) out[b] = proj_w @ h[b] + proj_b + x[b]   (M=512, N=1024, K=512)
    gemm_kernel<true, true><<<dim3(HW / BN, C_DIM / BM, BATCH), 256>>>(
        proj_w, h, out, C_DIM, HW, C_DIM,
        /*sAi*/ C_DIM, /*sAk*/ 1, /*sBk*/ HW, /*sBj*/ 1,
        0, nCHW, nCHW, 1.0f, proj_b, x, nCHW);

    (void)in_sizes; (void)n_in; (void)out_size;
}

// round 6
// speedup vs baseline: 3.0893x; 3.0893x over previous
#include <cuda_runtime.h>
#include <cuda_bf16.h>
#include <cstdint>
#include <math.h>

#define BATCH 16
#define C_DIM 512
#define HW    1024
#define GROUPS 32
#define CPG   (C_DIM / GROUPS)        // 16
#define GROUP_ELEMS (CPG * HW)        // 16384

// ---------------------------------------------------------------------------
// PTX helpers (sm_80-baseline features only: mma.sync, ldmatrix, cp.async)
// ---------------------------------------------------------------------------
__device__ __forceinline__ uint32_t smem_u32(const void* p) {
    uint32_t a;
    asm("{ .reg .u64 t; cvta.to.shared.u64 t, %1; cvt.u32.u64 %0, t; }"
        : "=r"(a) : "l"(p));
    return a;
}

__device__ __forceinline__ void ldmatrix_x4(uint32_t* r, uint32_t addr) {
    asm volatile("ldmatrix.sync.aligned.m8n8.x4.shared.b16 {%0,%1,%2,%3}, [%4];"
        : "=r"(r[0]), "=r"(r[1]), "=r"(r[2]), "=r"(r[3]) : "r"(addr));
}

__device__ __forceinline__ void mma_bf16(float* c, const uint32_t* a, const uint32_t* b) {
    asm volatile(
        "mma.sync.aligned.m16n8k16.row.col.f32.bf16.bf16.f32 "
        "{%0,%1,%2,%3}, {%4,%5,%6,%7}, {%8,%9}, {%0,%1,%2,%3};"
        : "+f"(c[0]), "+f"(c[1]), "+f"(c[2]), "+f"(c[3])
        : "r"(a[0]), "r"(a[1]), "r"(a[2]), "r"(a[3]), "r"(b[0]), "r"(b[1]));
}

__device__ __forceinline__ void cp16(uint32_t dst, const void* src) {
    asm volatile("cp.async.cg.shared.global [%0], [%1], 16;" :: "r"(dst), "l"(src) : "memory");
}
#define CP_COMMIT() asm volatile("cp.async.commit_group;" ::: "memory")

// ---------------------------------------------------------------------------
// scratch (static device arrays; allocations are forbidden)
// ---------------------------------------------------------------------------
__device__ float g_xn[BATCH * C_DIM * HW];                 // 33.5 MB
__device__ float g_S [BATCH * HW * HW];                    // 67 MB
__device__ __nv_bfloat16 g_xnT_h[BATCH * HW * C_DIM], g_xnT_l[BATCH * HW * C_DIM];
__device__ __nv_bfloat16 g_qk_h [BATCH * HW * HW],    g_qk_l [BATCH * HW * HW];
__device__ __nv_bfloat16 g_v_h  [BATCH * C_DIM * HW], g_v_l  [BATCH * C_DIM * HW];
__device__ __nv_bfloat16 g_at_h [BATCH * HW * HW],    g_at_l [BATCH * HW * HW];
__device__ __nv_bfloat16 g_h_h  [BATCH * HW * C_DIM], g_h_l  [BATCH * HW * C_DIM];
__device__ __nv_bfloat16 g_wq_h [3 * C_DIM * C_DIM],  g_wq_l [3 * C_DIM * C_DIM];
__device__ __nv_bfloat16 g_wp_h [C_DIM * C_DIM],      g_wp_l [C_DIM * C_DIM];

// ---------------------------------------------------------------------------
// GroupNorm (fp32 out, [C, HW] per batch)
// ---------------------------------------------------------------------------
__global__ __launch_bounds__(256) void groupnorm_kernel(
    const float* __restrict__ x, const float* __restrict__ w,
    const float* __restrict__ b, float* __restrict__ out)
{
    const int bg = blockIdx.x;
    const int g  = bg & (GROUPS - 1);
    const float* xp = x   + (size_t)bg * GROUP_ELEMS;
    float*       op = out + (size_t)bg * GROUP_ELEMS;
    const int tid = threadIdx.x;

    float s = 0.f, ss = 0.f;
    for (int i = tid; i < GROUP_ELEMS; i += 256) {
        float v = xp[i]; s += v; ss += v * v;
    }
    __shared__ float r0[256], r1[256];
    r0[tid] = s; r1[tid] = ss;
    __syncthreads();
    for (int st = 128; st > 0; st >>= 1) {
        if (tid < st) { r0[tid] += r0[tid + st]; r1[tid] += r1[tid + st]; }
        __syncthreads();
    }
    const float mean = r0[0] * (1.0f / GROUP_ELEMS);
    const float var  = r1[0] * (1.0f / GROUP_ELEMS) - mean * mean;
    const float inv  = rsqrtf(var + 1e-5f);
    for (int i = tid; i < GROUP_ELEMS; i += 256) {
        int c = g * CPG + (i >> 10);
        op[i] = (xp[i] - mean) * inv * w[c] + b[c];
    }
}

// ---------------------------------------------------------------------------
// transpose + bf16 hi/lo convert: xn [C, HW] -> xnT [HW, C]
// ---------------------------------------------------------------------------
__global__ __launch_bounds__(256) void transpose_cvt(
    const float* __restrict__ xn,
    __nv_bfloat16* __restrict__ th, __nv_bfloat16* __restrict__ tl)
{
    __shared__ float t[32][33];
    const int bz = blockIdx.z;
    const int c0 = blockIdx.y * 32, w0 = blockIdx.x * 32;
    const float* p = xn + (size_t)bz * (C_DIM * HW);
    const int tx = threadIdx.x, ty = threadIdx.y;
#pragma unroll
    for (int r = 0; r < 4; r++)
        t[ty + r * 8][tx] = p[(size_t)(c0 + ty + r * 8) * HW + w0 + tx];
    __syncthreads();
    __nv_bfloat16* oh = th + (size_t)bz * (HW * C_DIM);
    __nv_bfloat16* ol = tl + (size_t)bz * (HW * C_DIM);
#pragma unroll
    for (int r = 0; r < 4; r++) {
        float v = t[tx][ty + r * 8];
        size_t o = (size_t)(w0 + ty + r * 8) * C_DIM + c0 + tx;
        __nv_bfloat16 h = __float2bfloat16(v);
        oh[o] = h;
        ol[o] = __float2bfloat16(v - __bfloat162float(h));
    }
}

// elementwise fp32 -> bf16 hi/lo (weights)
__global__ __launch_bounds__(256) void cvt_kernel(
    const float* __restrict__ s, __nv_bfloat16* __restrict__ h,
    __nv_bfloat16* __restrict__ l, int n)
{
    int i = blockIdx.x * 256 + threadIdx.x;
    if (i < n) {
        float v = s[i];
        __nv_bfloat16 x = __float2bfloat16(v);
        h[i] = x;
        l[i] = __float2bfloat16(v - __bfloat162float(x));
    }
}

// ---------------------------------------------------------------------------
// softmax over 1024 + bf16 hi/lo convert
// ---------------------------------------------------------------------------
__global__ __launch_bounds__(256) void softmax_cvt(
    const float* __restrict__ S,
    __nv_bfloat16* __restrict__ ah, __nv_bfloat16* __restrict__ al)
{
    const size_t roff = (size_t)blockIdx.x * HW;
    const int tid = threadIdx.x;
    float4 v = reinterpret_cast<const float4*>(S + roff)[tid];
    __shared__ float red[256];
    float m = fmaxf(fmaxf(v.x, v.y), fmaxf(v.z, v.w));
    red[tid] = m; __syncthreads();
    for (int st = 128; st > 0; st >>= 1) {
        if (tid < st) red[tid] = fmaxf(red[tid], red[tid + st]);
        __syncthreads();
    }
    m = red[0]; __syncthreads();
    v.x = __expf(v.x - m); v.y = __expf(v.y - m);
    v.z = __expf(v.z - m); v.w = __expf(v.w - m);
    red[tid] = v.x + v.y + v.z + v.w; __syncthreads();
    for (int st = 128; st > 0; st >>= 1) {
        if (tid < st) red[tid] += red[tid + st];
        __syncthreads();
    }
    const float inv = 1.0f / red[0];
    float p[4] = { v.x * inv, v.y * inv, v.z * inv, v.w * inv };
    __align__(8) __nv_bfloat16 h4[4], l4[4];
#pragma unroll
    for (int t = 0; t < 4; t++) {
        h4[t] = __float2bfloat16(p[t]);
        l4[t] = __float2bfloat16(p[t] - __bfloat162float(h4[t]));
    }
    *reinterpret_cast<uint2*>(ah + roff + tid * 4) = *reinterpret_cast<const uint2*>(h4);
    *reinterpret_cast<uint2*>(al + roff + tid * 4) = *reinterpret_cast<const uint2*>(l4);
}

// ---------------------------------------------------------------------------
// HMMA bf16x3 GEMM: D[i,j] = sum_k A[i,k]*B[j,k]  (A:[M,K] ldA, B:[N,K] ldB,
// both hi+lo bf16). CTA 128x128, K-chunk 64, 256 thr, cp.async double buffer.
// MODE 0: QKV epilogue (bias per col, q-scale, q/k row-major, v transposed)
// MODE 1: plain fp32 out (S)
// MODE 2: bf16 hi/lo out (h)
// MODE 3: fp32 out + bias per row + residual
// ---------------------------------------------------------------------------
#define STAGE_BYTES 65536                 // 4 tiles x 16KB
#define GEMM_SMEM   (2 * STAGE_BYTES)     // 128KB

// one 128x64 bf16 tile, rows = 128B, xor-swizzled in 16B units
__device__ __forceinline__ void load_tile_async(
    const __nv_bfloat16* __restrict__ g, int ld, uint32_t sbase, int tid)
{
#pragma unroll
    for (int r = 0; r < 4; r++) {
        int idx = r * 256 + tid;
        int row = idx >> 3, c = idx & 7;
        uint32_t off = (uint32_t)(row * 128) + (uint32_t)((c ^ (row & 7)) << 4);
        cp16(sbase + off, g + (size_t)row * ld + c * 8);
    }
}

template<int MODE>
__global__ void __launch_bounds__(256, 1) hmma_gemm(
    const __nv_bfloat16* __restrict__ Ah, const __nv_bfloat16* __restrict__ Al,
    long bsA, int ldA,
    const __nv_bfloat16* __restrict__ Bh, const __nv_bfloat16* __restrict__ Bl,
    long bsB, int ldB,
    int K, int ldD, long bsD,
    float* __restrict__ po0,
    __nv_bfloat16* __restrict__ po1, __nv_bfloat16* __restrict__ po2,
    __nv_bfloat16* __restrict__ po3, __nv_bfloat16* __restrict__ po4,
    const float* __restrict__ bias, const float* __restrict__ res, long bsR,
    float qscale)
{
    extern __shared__ char smem[];
    const uint32_t sb = smem_u32(smem);
    const int tid = threadIdx.x, wid = tid >> 5, lane = tid & 31;
    const int wm = wid >> 2, wn = wid & 3;          // warps 2(M) x 4(N)
    const int bz = blockIdx.z;
    const int m0 = blockIdx.y << 7, j0 = blockIdx.x << 7;

    const __nv_bfloat16* a_h = Ah + (size_t)bz * bsA + (size_t)m0 * ldA;
    const __nv_bfloat16* a_l = Al + (size_t)bz * bsA + (size_t)m0 * ldA;
    const __nv_bfloat16* b_h = Bh + (size_t)bz * bsB + (size_t)j0 * ldB;
    const __nv_bfloat16* b_l = Bl + (size_t)bz * bsB + (size_t)j0 * ldB;

    const int NC = K >> 6;

    // prologue: stage 0
    load_tile_async(a_h, ldA, sb + 0,     tid);
    load_tile_async(a_l, ldA, sb + 16384, tid);
    load_tile_async(b_h, ldB, sb + 32768, tid);
    load_tile_async(b_l, ldB, sb + 49152, tid);
    CP_COMMIT();

    float acc[4][4][4];
#pragma unroll
    for (int i = 0; i < 4; i++)
#pragma unroll
        for (int j = 0; j < 4; j++)
#pragma unroll
            for (int t = 0; t < 4; t++) acc[i][j][t] = 0.f;

    const int lr = lane & 15, lc = lane >> 4;

    for (int ch = 0; ch < NC; ch++) {
        if (ch + 1 < NC) {
            const uint32_t nsb = sb + (uint32_t)(((ch + 1) & 1) * STAGE_BYTES);
            const size_t ko = (size_t)(ch + 1) << 6;
            load_tile_async(a_h + ko, ldA, nsb + 0,     tid);
            load_tile_async(a_l + ko, ldA, nsb + 16384, tid);
            load_tile_async(b_h + ko, ldB, nsb + 32768, tid);
            load_tile_async(b_l + ko, ldB, nsb + 49152, tid);
            CP_COMMIT();
            asm volatile("cp.async.wait_group 1;" ::: "memory");
        } else {
            asm volatile("cp.async.wait_group 0;" ::: "memory");
        }
        __syncthreads();

        const uint32_t sa = sb + (uint32_t)((ch & 1) * STAGE_BYTES);
#pragma unroll
        for (int ks = 0; ks < 4; ks++) {
            uint32_t ah[4][4], al[4][4], bh[4][2], bl[4][2];
            const int c = ks * 2 + lc;
#pragma unroll
            for (int mt = 0; mt < 4; mt++) {
                const int row = wm * 64 + mt * 16 + lr;
                const uint32_t addr = sa + (uint32_t)(row * 128)
                                    + (uint32_t)(((c ^ (row & 7)) << 4));
                ldmatrix_x4(ah[mt], addr);
                ldmatrix_x4(al[mt], addr + 16384);
            }
#pragma unroll
            for (int bt = 0; bt < 2; bt++) {
                const int row = wn * 32 + bt * 16 + lr;
                const uint32_t addr = sa + 32768 + (uint32_t)(row * 128)
                                    + (uint32_t)(((c ^ (row & 7)) << 4));
                uint32_t t0[4], t1[4];
                ldmatrix_x4(t0, addr);
                ldmatrix_x4(t1, addr + 16384);
                bh[bt * 2][0] = t0[0]; bh[bt * 2][1] = t0[2];
                bh[bt * 2 + 1][0] = t0[1]; bh[bt * 2 + 1][1] = t0[3];
                bl[bt * 2][0] = t1[0]; bl[bt * 2][1] = t1[2];
                bl[bt * 2 + 1][0] = t1[1]; bl[bt * 2 + 1][1] = t1[3];
            }
#pragma unroll
            for (int mt = 0; mt < 4; mt++)
#pragma unroll
                for (int nt = 0; nt < 4; nt++) {
                    mma_bf16(acc[mt][nt], ah[mt], bh[nt]);
                    mma_bf16(acc[mt][nt], ah[mt], bl[nt]);
                    mma_bf16(acc[mt][nt], al[mt], bh[nt]);
                }
        }
        __syncthreads();
    }

    // ------------------------- epilogue -------------------------
    const int g  = lane >> 2;
    const int tg = lane & 3;

    if (MODE == 0 && j0 >= 1024) {
        // v: stage transposed through smem, then coalesced hi/lo store [c][n]
        float* smf = reinterpret_cast<float*>(smem);
#pragma unroll
        for (int mt = 0; mt < 4; mt++)
#pragma unroll
            for (int nt = 0; nt < 4; nt++) {
                const int r0 = wm * 64 + mt * 16 + g;
                const int cc = wn * 32 + nt * 8 + 2 * tg;
                smf[(cc)     * 129 + r0]     = acc[mt][nt][0];
                smf[(cc + 1) * 129 + r0]     = acc[mt][nt][1];
                smf[(cc)     * 129 + r0 + 8] = acc[mt][nt][2];
                smf[(cc + 1) * 129 + r0 + 8] = acc[mt][nt][3];
            }
        __syncthreads();
        const size_t vb = (size_t)bz * ((size_t)C_DIM * HW);
#pragma unroll 4
        for (int i = 0; i < 64; i++) {
            const int idx = tid + i * 256;
            const int cc = idx >> 7, n = idx & 127;
            float v = smf[cc * 129 + n] + bias[j0 + cc];
            __nv_bfloat16 h = __float2bfloat16(v);
            __nv_bfloat16 l = __float2bfloat16(v - __bfloat162float(h));
            const size_t o = vb + (size_t)(j0 - 1024 + cc) * HW + m0 + n;
            po3[o] = h; po4[o] = l;
        }
        return;
    }

#pragma unroll
    for (int mt = 0; mt < 4; mt++) {
#pragma unroll
        for (int nt = 0; nt < 4; nt++) {
            const int r0  = m0 + wm * 64 + mt * 16 + g;
            const int col = j0 + wn * 32 + nt * 8 + 2 * tg;
            float v0 = acc[mt][nt][0], v1 = acc[mt][nt][1];
            float v2 = acc[mt][nt][2], v3 = acc[mt][nt][3];

            if (MODE == 0) {
                const float b0 = bias[col], b1 = bias[col + 1];
                v0 += b0; v1 += b1; v2 += b0; v3 += b1;
                if (j0 < 512) { v0 *= qscale; v1 *= qscale; v2 *= qscale; v3 *= qscale; }
            } else if (MODE == 3) {
                const float rb0 = bias[r0], rb1 = bias[r0 + 8];
                const float* rp = res + (size_t)bz * bsR;
                v0 += rb0 + rp[(size_t)r0 * ldD + col];
                v1 += rb0 + rp[(size_t)r0 * ldD + col + 1];
                v2 += rb1 + rp[(size_t)(r0 + 8) * ldD + col];
                v3 += rb1 + rp[(size_t)(r0 + 8) * ldD + col + 1];
            }

            if (MODE == 1 || MODE == 3) {
                float* op = po0 + (size_t)bz * bsD;
                *reinterpret_cast<float2*>(op + (size_t)r0 * ldD + col)       = make_float2(v0, v1);
                *reinterpret_cast<float2*>(op + (size_t)(r0 + 8) * ldD + col) = make_float2(v2, v3);
            } else {
                // MODE 0 (q/k) and MODE 2: hi/lo bf16 pair stores
                const size_t o0 = (size_t)bz * bsD + (size_t)r0 * ldD + col;
                const size_t o1 = (size_t)bz * bsD + (size_t)(r0 + 8) * ldD + col;
                __nv_bfloat16 h0 = __float2bfloat16(v0), h1 = __float2bfloat16(v1);
                __nv_bfloat16 h2 = __float2bfloat16(v2), h3 = __float2bfloat16(v3);
                uint32_t hw0 = (uint32_t)__bfloat16_as_ushort(h0) | ((uint32_t)__bfloat16_as_ushort(h1) << 16);
                uint32_t hw1 = (uint32_t)__bfloat16_as_ushort(h2) | ((uint32_t)__bfloat16_as_ushort(h3) << 16);
                __nv_bfloat16 l0 = __float2bfloat16(v0 - __bfloat162float(h0));
                __nv_bfloat16 l1 = __float2bfloat16(v1 - __bfloat162float(h1));
                __nv_bfloat16 l2 = __float2bfloat16(v2 - __bfloat162float(h2));
                __nv_bfloat16 l3 = __float2bfloat16(v3 - __bfloat162float(h3));
                uint32_t lw0 = (uint32_t)__bfloat16_as_ushort(l0) | ((uint32_t)__bfloat16_as_ushort(l1) << 16);
                uint32_t lw1 = (uint32_t)__bfloat16_as_ushort(l2) | ((uint32_t)__bfloat16_as_ushort(l3) << 16);
                *reinterpret_cast<uint32_t*>(po1 + o0) = hw0;
                *reinterpret_cast<uint32_t*>(po1 + o1) = hw1;
                *reinterpret_cast<uint32_t*>(po2 + o0) = lw0;
                *reinterpret_cast<uint32_t*>(po2 + o1) = lw1;
            }
        }
    }
}

// ---------------------------------------------------------------------------
extern "C" void kernel_launch(void* const* d_in, const int* in_sizes, int n_in,
                              void* d_out, int out_size)
{
    const float* x      = (const float*)d_in[0];
    const float* norm_w = (const float*)d_in[1];
    const float* norm_b = (const float*)d_in[2];
    const float* qkv_w  = (const float*)d_in[3];
    const float* qkv_b  = (const float*)d_in[4];
    const float* proj_w = (const float*)d_in[5];
    const float* proj_b = (const float*)d_in[6];
    float* out = (float*)d_out;

    float *xn, *S;
    __nv_bfloat16 *xnT_h, *xnT_l, *qk_h, *qk_l, *v_h, *v_l, *at_h, *at_l, *h_h, *h_l;
    __nv_bfloat16 *wq_h, *wq_l, *wp_h, *wp_l;
    cudaGetSymbolAddress((void**)&xn,    g_xn);
    cudaGetSymbolAddress((void**)&S,     g_S);
    cudaGetSymbolAddress((void**)&xnT_h, g_xnT_h);  cudaGetSymbolAddress((void**)&xnT_l, g_xnT_l);
    cudaGetSymbolAddress((void**)&qk_h,  g_qk_h);   cudaGetSymbolAddress((void**)&qk_l,  g_qk_l);
    cudaGetSymbolAddress((void**)&v_h,   g_v_h);    cudaGetSymbolAddress((void**)&v_l,   g_v_l);
    cudaGetSymbolAddress((void**)&at_h,  g_at_h);   cudaGetSymbolAddress((void**)&at_l,  g_at_l);
    cudaGetSymbolAddress((void**)&h_h,   g_h_h);    cudaGetSymbolAddress((void**)&h_l,   g_h_l);
    cudaGetSymbolAddress((void**)&wq_h,  g_wq_h);   cudaGetSymbolAddress((void**)&wq_l,  g_wq_l);
    cudaGetSymbolAddress((void**)&wp_h,  g_wp_h);   cudaGetSymbolAddress((void**)&wp_l,  g_wp_l);

    cudaFuncSetAttribute(hmma_gemm<0>, cudaFuncAttributeMaxDynamicSharedMemorySize, GEMM_SMEM);
    cudaFuncSetAttribute(hmma_gemm<1>, cudaFuncAttributeMaxDynamicSharedMemorySize, GEMM_SMEM);
    cudaFuncSetAttribute(hmma_gemm<2>, cudaFuncAttributeMaxDynamicSharedMemorySize, GEMM_SMEM);
    cudaFuncSetAttribute(hmma_gemm<3>, cudaFuncAttributeMaxDynamicSharedMemorySize, GEMM_SMEM);

    const long nCHW = (long)C_DIM * HW;   // 524288
    const long nSS  = (long)HW * HW;      // 1048576
    const float qscale = 0.04419417382415922f;  // 1/sqrt(512)

    // 1) GroupNorm -> xn [C, HW] fp32
    groupnorm_kernel<<<BATCH * GROUPS, 256>>>(x, norm_w, norm_b, xn);

    // 2) transpose+convert -> xnT [HW, C] bf16 hi/lo
    transpose_cvt<<<dim3(HW / 32, C_DIM / 32, BATCH), dim3(32, 8)>>>(xn, xnT_h, xnT_l);

    // 3) weight conversions
    cvt_kernel<<<(3 * C_DIM * C_DIM + 255) / 256, 256>>>(qkv_w, wq_h, wq_l, 3 * C_DIM * C_DIM);
    cvt_kernel<<<(C_DIM * C_DIM + 255) / 256, 256>>>(proj_w, wp_h, wp_l, C_DIM * C_DIM);

    // 4) QKV: D[n,o] = xnT[n,:] . W[o,:] + b[o];  q scaled; v stored transposed
    hmma_gemm<0><<<dim3(12, 8, BATCH), 256, GEMM_SMEM>>>(
        xnT_h, xnT_l, nCHW, C_DIM,
        wq_h, wq_l, 0, C_DIM,
        C_DIM, HW, nSS,
        nullptr, qk_h, qk_l, v_h, v_l, qkv_b, nullptr, 0, qscale);

    // 5) S[n,m] = q[n,:] . k[m,:]   (q pre-scaled)
    hmma_gemm<1><<<dim3(8, 8, BATCH), 256, GEMM_SMEM>>>(
        qk_h, qk_l, nSS, HW,
        qk_h + 512, qk_l + 512, nSS, HW,
        C_DIM, HW, nSS,
        S, nullptr, nullptr, nullptr, nullptr, nullptr, nullptr, 0, 1.0f);

    // 6) softmax + convert
    softmax_cvt<<<BATCH * HW, 256>>>(S, at_h, at_l);

    // 7) h[n,c] = attn[n,:] . v[c,:]   (v stored [c, m])
    hmma_gemm<2><<<dim3(4, 8, BATCH), 256, GEMM_SMEM>>>(
        at_h, at_l, nSS, HW,
        v_h, v_l, nCHW, HW,
        HW, C_DIM, nCHW,
        nullptr, h_h, h_l, nullptr, nullptr, nullptr, nullptr, 0, 1.0f);

    // 8) out[o,n] = proj_w[o,:] . h[n,:] + proj_b[o] + x[o,n]
    hmma_gemm<3><<<dim3(8, 4, BATCH), 256, GEMM_SMEM>>>(
        wp_h, wp_l, 0, C_DIM,
        h_h, h_l, nCHW, C_DIM,
        C_DIM, HW, nCHW,
        out, nullptr, nullptr, nullptr, nullptr, proj_b, x, nCHW, 1.0f);

    (void)in_sizes; (void)n_in; (void)out_size;
}

// round 7
// speedup vs baseline: 4.6161x; 1.4942x over previous
#include <cuda_runtime.h>
#include <cuda_fp16.h>
#include <cstdint>
#include <math.h>

#define BATCH 16
#define C_DIM 512
#define HW    1024
#define GROUPS 32
#define CPG   (C_DIM / GROUPS)        // 16
#define GROUP_ELEMS (CPG * HW)        // 16384

// ---------------------------------------------------------------------------
// PTX helpers (sm_80-baseline features only: mma.sync, ldmatrix, cp.async)
// ---------------------------------------------------------------------------
__device__ __forceinline__ uint32_t smem_u32(const void* p) {
    uint32_t a;
    asm("{ .reg .u64 t; cvta.to.shared.u64 t, %1; cvt.u32.u64 %0, t; }"
        : "=r"(a) : "l"(p));
    return a;
}

__device__ __forceinline__ void ldmatrix_x4(uint32_t* r, uint32_t addr) {
    asm volatile("ldmatrix.sync.aligned.m8n8.x4.shared.b16 {%0,%1,%2,%3}, [%4];"
        : "=r"(r[0]), "=r"(r[1]), "=r"(r[2]), "=r"(r[3]) : "r"(addr));
}

__device__ __forceinline__ void mma_f16(float* c, const uint32_t* a, const uint32_t* b) {
    asm volatile(
        "mma.sync.aligned.m16n8k16.row.col.f32.f16.f16.f32 "
        "{%0,%1,%2,%3}, {%4,%5,%6,%7}, {%8,%9}, {%0,%1,%2,%3};"
        : "+f"(c[0]), "+f"(c[1]), "+f"(c[2]), "+f"(c[3])
        : "r"(a[0]), "r"(a[1]), "r"(a[2]), "r"(a[3]), "r"(b[0]), "r"(b[1]));
}

__device__ __forceinline__ void cp16(uint32_t dst, const void* src) {
    asm volatile("cp.async.cg.shared.global [%0], [%1], 16;" :: "r"(dst), "l"(src) : "memory");
}
#define CP_COMMIT() asm volatile("cp.async.commit_group;" ::: "memory")

__device__ __forceinline__ uint32_t pack2h(__half a, __half b) {
    return (uint32_t)__half_as_ushort(a) | ((uint32_t)__half_as_ushort(b) << 16);
}

// ---------------------------------------------------------------------------
// scratch (static device arrays; allocations are forbidden)
// ---------------------------------------------------------------------------
__device__ float  g_S   [BATCH * HW * HW];                    // 67 MB
__device__ __half g_xnT_h[BATCH * HW * C_DIM], g_xnT_l[BATCH * HW * C_DIM];
__device__ __half g_q_h [BATCH * HW * C_DIM],  g_q_l [BATCH * HW * C_DIM];
__device__ __half g_k   [BATCH * HW * C_DIM];
__device__ __half g_v   [BATCH * C_DIM * HW];
__device__ __half g_at_h[BATCH * HW * HW],     g_at_l[BATCH * HW * HW];
__device__ __half g_h_h [BATCH * HW * C_DIM],  g_h_l [BATCH * HW * C_DIM];
__device__ __half g_wq  [3 * C_DIM * C_DIM];
__device__ __half g_wp  [C_DIM * C_DIM];

// ---------------------------------------------------------------------------
// Fused GroupNorm + transpose + fp16 hi/lo split: x [C,HW] -> xnT [HW,C]
// one block per (b, g); group region contiguous (16 ch x 1024)
// ---------------------------------------------------------------------------
__global__ __launch_bounds__(256) void gn_transpose_cvt(
    const float* __restrict__ x, const float* __restrict__ w,
    const float* __restrict__ b,
    __half* __restrict__ th, __half* __restrict__ tl)
{
    const int bg = blockIdx.x;
    const int bz = bg >> 5, g = bg & 31;
    const float* xp = x + (size_t)bg * GROUP_ELEMS;
    const int tid = threadIdx.x;

    float s = 0.f, ss = 0.f;
    for (int i = tid; i < GROUP_ELEMS; i += 256) {
        float v = xp[i]; s += v; ss += v * v;
    }
    __shared__ float r0[256], r1[256];
    r0[tid] = s; r1[tid] = ss;
    __syncthreads();
    for (int st = 128; st > 0; st >>= 1) {
        if (tid < st) { r0[tid] += r0[tid + st]; r1[tid] += r1[tid + st]; }
        __syncthreads();
    }
    const float mean = r0[0] * (1.0f / GROUP_ELEMS);
    const float var  = r1[0] * (1.0f / GROUP_ELEMS) - mean * mean;
    const float inv  = rsqrtf(var + 1e-5f);

    __shared__ float t[CPG][257];
    __shared__ float sca[CPG], shf[CPG];
    if (tid < CPG) {
        float a = w[g * CPG + tid] * inv;
        sca[tid] = a;
        shf[tid] = b[g * CPG + tid] - mean * a;
    }
    __syncthreads();

    __half* oh = th + (size_t)bz * (HW * C_DIM) + g * CPG;
    __half* ol = tl + (size_t)bz * (HW * C_DIM) + g * CPG;

    for (int wb = 0; wb < 4; wb++) {
#pragma unroll
        for (int r = 0; r < CPG; r++)
            t[r][tid] = xp[r * HW + wb * 256 + tid];
        __syncthreads();
        __align__(16) __half hh[CPG], ll[CPG];
#pragma unroll
        for (int c = 0; c < CPG; c++) {
            float v = t[c][tid] * sca[c] + shf[c];
            __half h = __float2half(v);
            hh[c] = h;
            ll[c] = __float2half(v - __half2float(h));
        }
        const size_t o = (size_t)(wb * 256 + tid) * C_DIM;
        *reinterpret_cast<uint4*>(oh + o)     = *reinterpret_cast<const uint4*>(hh);
        *reinterpret_cast<uint4*>(oh + o + 8) = *reinterpret_cast<const uint4*>(hh + 8);
        *reinterpret_cast<uint4*>(ol + o)     = *reinterpret_cast<const uint4*>(ll);
        *reinterpret_cast<uint4*>(ol + o + 8) = *reinterpret_cast<const uint4*>(ll + 8);
        __syncthreads();
    }
}

// elementwise fp32 -> single fp16 (weights)
__global__ __launch_bounds__(256) void cvt_half(
    const float* __restrict__ s, __half* __restrict__ h, int n)
{
    int i = blockIdx.x * 256 + threadIdx.x;
    if (i < n) h[i] = __float2half(s[i]);
}

// ---------------------------------------------------------------------------
// softmax over 1024 + fp16 hi/lo convert
// ---------------------------------------------------------------------------
__global__ __launch_bounds__(256) void softmax_cvt(
    const float* __restrict__ S,
    __half* __restrict__ ah, __half* __restrict__ al)
{
    const size_t roff = (size_t)blockIdx.x * HW;
    const int tid = threadIdx.x;
    float4 v = reinterpret_cast<const float4*>(S + roff)[tid];
    __shared__ float red[256];
    float m = fmaxf(fmaxf(v.x, v.y), fmaxf(v.z, v.w));
    red[tid] = m; __syncthreads();
    for (int st = 128; st > 0; st >>= 1) {
        if (tid < st) red[tid] = fmaxf(red[tid], red[tid + st]);
        __syncthreads();
    }
    m = red[0]; __syncthreads();
    v.x = __expf(v.x - m); v.y = __expf(v.y - m);
    v.z = __expf(v.z - m); v.w = __expf(v.w - m);
    red[tid] = v.x + v.y + v.z + v.w; __syncthreads();
    for (int st = 128; st > 0; st >>= 1) {
        if (tid < st) red[tid] += red[tid + st];
        __syncthreads();
    }
    const float inv = 1.0f / red[0];
    float p[4] = { v.x * inv, v.y * inv, v.z * inv, v.w * inv };
    __align__(8) __half h4[4], l4[4];
#pragma unroll
    for (int t = 0; t < 4; t++) {
        h4[t] = __float2half(p[t]);
        l4[t] = __float2half(p[t] - __half2float(h4[t]));
    }
    *reinterpret_cast<uint2*>(ah + roff + tid * 4) = *reinterpret_cast<const uint2*>(h4);
    *reinterpret_cast<uint2*>(al + roff + tid * 4) = *reinterpret_cast<const uint2*>(l4);
}

// ---------------------------------------------------------------------------
// HMMA fp16x2 GEMM: D[i,j] = sum_k A[i,k]*B[j,k]
// A split hi/lo fp16 ([M,K] ldA), B single fp16 ([N,K] ldB).
// CTA 128x128, K-chunk 64, 256 thr, cp.async double buffer (3 tiles/stage).
// MODE 0: QKV epilogue (bias per col; q scaled hi/lo, k single, v transposed)
// MODE 1: plain fp32 out (S)
// MODE 2: fp16 hi/lo out, ld 512 (h)
// MODE 3: proj: transpose store + bias + residual -> out [o, n]
// ---------------------------------------------------------------------------
#define STAGE_BYTES 49152                 // 3 tiles x 16KB
#define GEMM_SMEM   98304                 // 2 stages (also covers epilogue smf)

__device__ __forceinline__ void load_tile_async(
    const __half* __restrict__ g, int ld, uint32_t sbase, int tid)
{
#pragma unroll
    for (int r = 0; r < 4; r++) {
        int idx = r * 256 + tid;
        int row = idx >> 3, c = idx & 7;
        uint32_t off = (uint32_t)(row * 128) + (uint32_t)((c ^ (row & 7)) << 4);
        cp16(sbase + off, g + (size_t)row * ld + c * 8);
    }
}

template<int MODE>
__global__ void __launch_bounds__(256) hmma_gemm(
    const __half* __restrict__ Ah, const __half* __restrict__ Al,
    long bsA, int ldA,
    const __half* __restrict__ B_, long bsB, int ldB,
    int K, int ldD, long bsD,
    float* __restrict__ po0,
    __half* __restrict__ po1, __half* __restrict__ po2,
    __half* __restrict__ po3, __half* __restrict__ po4,
    const float* __restrict__ bias, const float* __restrict__ res, long bsR,
    float qscale)
{
    extern __shared__ char smem[];
    const uint32_t sb = smem_u32(smem);
    const int tid = threadIdx.x, wid = tid >> 5, lane = tid & 31;
    const int wm = wid >> 2, wn = wid & 3;          // warps 2(M) x 4(N)
    const int bz = blockIdx.z;
    const int m0 = blockIdx.y << 7, j0 = blockIdx.x << 7;

    const __half* a_h = Ah + (size_t)bz * bsA + (size_t)m0 * ldA;
    const __half* a_l = Al + (size_t)bz * bsA + (size_t)m0 * ldA;
    const __half* b_s = B_ + (size_t)bz * bsB + (size_t)j0 * ldB;

    const int NC = K >> 6;

    load_tile_async(a_h, ldA, sb + 0,     tid);
    load_tile_async(a_l, ldA, sb + 16384, tid);
    load_tile_async(b_s, ldB, sb + 32768, tid);
    CP_COMMIT();

    float acc[4][4][4];
#pragma unroll
    for (int i = 0; i < 4; i++)
#pragma unroll
        for (int j = 0; j < 4; j++)
#pragma unroll
            for (int t = 0; t < 4; t++) acc[i][j][t] = 0.f;

    const int lr = lane & 15, lc = lane >> 4;

    for (int ch = 0; ch < NC; ch++) {
        if (ch + 1 < NC) {
            const uint32_t nsb = sb + (uint32_t)(((ch + 1) & 1) * STAGE_BYTES);
            const size_t ko = (size_t)(ch + 1) << 6;
            load_tile_async(a_h + ko, ldA, nsb + 0,     tid);
            load_tile_async(a_l + ko, ldA, nsb + 16384, tid);
            load_tile_async(b_s + ko, ldB, nsb + 32768, tid);
            CP_COMMIT();
            asm volatile("cp.async.wait_group 1;" ::: "memory");
        } else {
            asm volatile("cp.async.wait_group 0;" ::: "memory");
        }
        __syncthreads();

        const uint32_t sa = sb + (uint32_t)((ch & 1) * STAGE_BYTES);
#pragma unroll
        for (int ks = 0; ks < 4; ks++) {
            uint32_t ah[4][4], al[4][4], bh[4][2];
            const int c = ks * 2 + lc;
#pragma unroll
            for (int mt = 0; mt < 4; mt++) {
                const int row = wm * 64 + mt * 16 + lr;
                const uint32_t addr = sa + (uint32_t)(row * 128)
                                    + (uint32_t)(((c ^ (row & 7)) << 4));
                ldmatrix_x4(ah[mt], addr);
                ldmatrix_x4(al[mt], addr + 16384);
            }
#pragma unroll
            for (int bt = 0; bt < 2; bt++) {
                const int row = wn * 32 + bt * 16 + lr;
                const uint32_t addr = sa + 32768 + (uint32_t)(row * 128)
                                    + (uint32_t)(((c ^ (row & 7)) << 4));
                uint32_t t0[4];
                ldmatrix_x4(t0, addr);
                bh[bt * 2][0] = t0[0]; bh[bt * 2][1] = t0[2];
                bh[bt * 2 + 1][0] = t0[1]; bh[bt * 2 + 1][1] = t0[3];
            }
#pragma unroll
            for (int mt = 0; mt < 4; mt++)
#pragma unroll
                for (int nt = 0; nt < 4; nt++) {
                    mma_f16(acc[mt][nt], ah[mt], bh[nt]);
                    mma_f16(acc[mt][nt], al[mt], bh[nt]);
                }
        }
        __syncthreads();
    }

    // ------------------------- epilogue -------------------------
    const int g  = lane >> 2;
    const int tg = lane & 3;

    if ((MODE == 0 && j0 >= 1024) || MODE == 3) {
        // stage fp32 tile transposed in smem: smf[col_local][row_local]
        float* smf = reinterpret_cast<float*>(smem);
#pragma unroll
        for (int mt = 0; mt < 4; mt++)
#pragma unroll
            for (int nt = 0; nt < 4; nt++) {
                const int rl = wm * 64 + mt * 16 + g;
                const int cl = wn * 32 + nt * 8 + 2 * tg;
                smf[(cl)     * 129 + rl]     = acc[mt][nt][0];
                smf[(cl + 1) * 129 + rl]     = acc[mt][nt][1];
                smf[(cl)     * 129 + rl + 8] = acc[mt][nt][2];
                smf[(cl + 1) * 129 + rl + 8] = acc[mt][nt][3];
            }
        __syncthreads();

        if (MODE == 0) {
            // v: out[c, n] single fp16, c = j0-1024+cl, n = m0+nl
            const size_t vb = (size_t)bz * ((size_t)C_DIM * HW);
#pragma unroll 4
            for (int i = 0; i < 32; i++) {
                const int idx = tid + i * 256;
                const int cl = idx >> 6, nl = (idx & 63) * 2;
                const float bv = bias[j0 + cl];
                float v0 = smf[cl * 129 + nl]     + bv;
                float v1 = smf[cl * 129 + nl + 1] + bv;
                const size_t o = vb + (size_t)(j0 - 1024 + cl) * HW + m0 + nl;
                *reinterpret_cast<uint32_t*>(po4 + o) =
                    pack2h(__float2half(v0), __float2half(v1));
            }
        } else {
            // proj: out[o, n] = D[n, o] + bias[o] + x[o, n]
            float* op = po0 + (size_t)bz * bsD;
            const float* rp = res + (size_t)bz * bsR;
#pragma unroll 4
            for (int i = 0; i < 16; i++) {
                const int idx = tid + i * 256;
                const int ol = idx >> 5, nl = (idx & 31) * 4;
                const float bv = bias[j0 + ol];
                const size_t o = (size_t)(j0 + ol) * HW + m0 + nl;
                float4 rv = *reinterpret_cast<const float4*>(rp + o);
                float4 vv;
                vv.x = smf[ol * 129 + nl]     + bv + rv.x;
                vv.y = smf[ol * 129 + nl + 1] + bv + rv.y;
                vv.z = smf[ol * 129 + nl + 2] + bv + rv.z;
                vv.w = smf[ol * 129 + nl + 3] + bv + rv.w;
                *reinterpret_cast<float4*>(op + o) = vv;
            }
        }
        return;
    }

#pragma unroll
    for (int mt = 0; mt < 4; mt++) {
#pragma unroll
        for (int nt = 0; nt < 4; nt++) {
            const int r0  = m0 + wm * 64 + mt * 16 + g;
            const int col = j0 + wn * 32 + nt * 8 + 2 * tg;
            float v0 = acc[mt][nt][0], v1 = acc[mt][nt][1];
            float v2 = acc[mt][nt][2], v3 = acc[mt][nt][3];

            if (MODE == 0) {
                const float b0 = bias[col], b1 = bias[col + 1];
                v0 += b0; v1 += b1; v2 += b0; v3 += b1;
            }

            if (MODE == 1) {
                float* op = po0 + (size_t)bz * bsD;
                *reinterpret_cast<float2*>(op + (size_t)r0 * ldD + col)       = make_float2(v0, v1);
                *reinterpret_cast<float2*>(op + (size_t)(r0 + 8) * ldD + col) = make_float2(v2, v3);
            } else if (MODE == 0 && col >= 512) {
                // k: single fp16, [n, 512]
                const size_t o0 = (size_t)bz * bsD + (size_t)r0 * 512 + (col - 512);
                const size_t o1 = (size_t)bz * bsD + (size_t)(r0 + 8) * 512 + (col - 512);
                *reinterpret_cast<uint32_t*>(po3 + o0) = pack2h(__float2half(v0), __float2half(v1));
                *reinterpret_cast<uint32_t*>(po3 + o1) = pack2h(__float2half(v2), __float2half(v3));
            } else {
                // MODE 0 q (scaled) / MODE 2 h: hi/lo fp16 pairs, ld 512
                if (MODE == 0) { v0 *= qscale; v1 *= qscale; v2 *= qscale; v3 *= qscale; }
                const size_t o0 = (size_t)bz * bsD + (size_t)r0 * 512 + col;
                const size_t o1 = (size_t)bz * bsD + (size_t)(r0 + 8) * 512 + col;
                __half h0 = __float2half(v0), h1 = __float2half(v1);
                __half h2 = __float2half(v2), h3 = __float2half(v3);
                *reinterpret_cast<uint32_t*>(po1 + o0) = pack2h(h0, h1);
                *reinterpret_cast<uint32_t*>(po1 + o1) = pack2h(h2, h3);
                *reinterpret_cast<uint32_t*>(po2 + o0) =
                    pack2h(__float2half(v0 - __half2float(h0)), __float2half(v1 - __half2float(h1)));
                *reinterpret_cast<uint32_t*>(po2 + o1) =
                    pack2h(__float2half(v2 - __half2float(h2)), __float2half(v3 - __half2float(h3)));
            }
        }
    }
}

// ---------------------------------------------------------------------------
extern "C" void kernel_launch(void* const* d_in, const int* in_sizes, int n_in,
                              void* d_out, int out_size)
{
    const float* x      = (const float*)d_in[0];
    const float* norm_w = (const float*)d_in[1];
    const float* norm_b = (const float*)d_in[2];
    const float* qkv_w  = (const float*)d_in[3];
    const float* qkv_b  = (const float*)d_in[4];
    const float* proj_w = (const float*)d_in[5];
    const float* proj_b = (const float*)d_in[6];
    float* out = (float*)d_out;

    float *S;
    __half *xnT_h, *xnT_l, *q_h, *q_l, *k_, *v_, *at_h, *at_l, *h_h, *h_l, *wq, *wp;
    cudaGetSymbolAddress((void**)&S,     g_S);
    cudaGetSymbolAddress((void**)&xnT_h, g_xnT_h);  cudaGetSymbolAddress((void**)&xnT_l, g_xnT_l);
    cudaGetSymbolAddress((void**)&q_h,   g_q_h);    cudaGetSymbolAddress((void**)&q_l,   g_q_l);
    cudaGetSymbolAddress((void**)&k_,    g_k);      cudaGetSymbolAddress((void**)&v_,    g_v);
    cudaGetSymbolAddress((void**)&at_h,  g_at_h);   cudaGetSymbolAddress((void**)&at_l,  g_at_l);
    cudaGetSymbolAddress((void**)&h_h,   g_h_h);    cudaGetSymbolAddress((void**)&h_l,   g_h_l);
    cudaGetSymbolAddress((void**)&wq,    g_wq);     cudaGetSymbolAddress((void**)&wp,    g_wp);

    cudaFuncSetAttribute(hmma_gemm<0>, cudaFuncAttributeMaxDynamicSharedMemorySize, GEMM_SMEM);
    cudaFuncSetAttribute(hmma_gemm<1>, cudaFuncAttributeMaxDynamicSharedMemorySize, GEMM_SMEM);
    cudaFuncSetAttribute(hmma_gemm<2>, cudaFuncAttributeMaxDynamicSharedMemorySize, GEMM_SMEM);
    cudaFuncSetAttribute(hmma_gemm<3>, cudaFuncAttributeMaxDynamicSharedMemorySize, GEMM_SMEM);

    const long nCHW = (long)C_DIM * HW;   // 524288
    const long nSS  = (long)HW * HW;      // 1048576
    const float qscale = 0.04419417382415922f;  // 1/sqrt(512)

    // 1) fused GroupNorm + transpose + fp16 split -> xnT [HW, C]
    gn_transpose_cvt<<<BATCH * GROUPS, 256>>>(x, norm_w, norm_b, xnT_h, xnT_l);

    // 2) weight conversions (single fp16)
    cvt_half<<<(3 * C_DIM * C_DIM + 255) / 256, 256>>>(qkv_w, wq, 3 * C_DIM * C_DIM);
    cvt_half<<<(C_DIM * C_DIM + 255) / 256, 256>>>(proj_w, wp, C_DIM * C_DIM);

    // 3) QKV: D[n,o] = xnT[n,:] . W[o,:] + b[o];  q hi/lo scaled, k single, v transposed
    hmma_gemm<0><<<dim3(12, 8, BATCH), 256, GEMM_SMEM>>>(
        xnT_h, xnT_l, nCHW, C_DIM,
        wq, 0, C_DIM,
        C_DIM, 512, nCHW,
        nullptr, q_h, q_l, k_, v_, qkv_b, nullptr, 0, qscale);

    // 4) S[n,m] = q[n,:] . k[m,:]   (q pre-scaled hi/lo, k single)
    hmma_gemm<1><<<dim3(8, 8, BATCH), 256, GEMM_SMEM>>>(
        q_h, q_l, nCHW, C_DIM,
        k_, nCHW, C_DIM,
        C_DIM, HW, nSS,
        S, nullptr, nullptr, nullptr, nullptr, nullptr, nullptr, 0, 1.0f);

    // 5) softmax + fp16 hi/lo convert
    softmax_cvt<<<BATCH * HW, 256>>>(S, at_h, at_l);

    // 6) h[n,c] = attn[n,:] . v[c,:]   (probs hi/lo, v single [c, m])
    hmma_gemm<2><<<dim3(4, 8, BATCH), 256, GEMM_SMEM>>>(
        at_h, at_l, nSS, HW,
        v_, nCHW, HW,
        HW, 512, nCHW,
        nullptr, h_h, h_l, nullptr, nullptr, nullptr, nullptr, 0, 1.0f);

    // 7) proj: D[n,o] = h[n,:] . wp[o,:]; out[o,n] = D + proj_b[o] + x[o,n]
    hmma_gemm<3><<<dim3(4, 8, BATCH), 256, GEMM_SMEM>>>(
        h_h, h_l, nCHW, C_DIM,
        wp, 0, C_DIM,
        C_DIM, HW, nCHW,
        out, nullptr, nullptr, nullptr, nullptr, proj_b, x, nCHW, 1.0f);

    (void)in_sizes; (void)n_in; (void)out_size;
}

// round 8
// speedup vs baseline: 7.5909x; 1.6445x over previous
#include <cuda_runtime.h>
#include <cuda_fp16.h>
#include <cstdint>
#include <math.h>

#define BATCH 16
#define C_DIM 512
#define HW    1024
#define GROUPS 32
#define CPG   (C_DIM / GROUPS)        // 16
#define GROUP_ELEMS (CPG * HW)        // 16384

// ---------------------------------------------------------------------------
// PTX helpers (sm_80-baseline features only: mma.sync, ldmatrix, cp.async)
// ---------------------------------------------------------------------------
__device__ __forceinline__ uint32_t smem_u32(const void* p) {
    uint32_t a;
    asm("{ .reg .u64 t; cvta.to.shared.u64 t, %1; cvt.u32.u64 %0, t; }"
        : "=r"(a) : "l"(p));
    return a;
}

__device__ __forceinline__ void ldmatrix_x4(uint32_t* r, uint32_t addr) {
    asm volatile("ldmatrix.sync.aligned.m8n8.x4.shared.b16 {%0,%1,%2,%3}, [%4];"
        : "=r"(r[0]), "=r"(r[1]), "=r"(r[2]), "=r"(r[3]) : "r"(addr));
}

__device__ __forceinline__ void mma_f16(float* c, const uint32_t* a, const uint32_t* b) {
    asm volatile(
        "mma.sync.aligned.m16n8k16.row.col.f32.f16.f16.f32 "
        "{%0,%1,%2,%3}, {%4,%5,%6,%7}, {%8,%9}, {%0,%1,%2,%3};"
        : "+f"(c[0]), "+f"(c[1]), "+f"(c[2]), "+f"(c[3])
        : "r"(a[0]), "r"(a[1]), "r"(a[2]), "r"(a[3]), "r"(b[0]), "r"(b[1]));
}

__device__ __forceinline__ void cp16(uint32_t dst, const void* src) {
    asm volatile("cp.async.cg.shared.global [%0], [%1], 16;" :: "r"(dst), "l"(src) : "memory");
}
#define CP_COMMIT() asm volatile("cp.async.commit_group;" ::: "memory")

__device__ __forceinline__ uint32_t pack2h(__half a, __half b) {
    return (uint32_t)__half_as_ushort(a) | ((uint32_t)__half_as_ushort(b) << 16);
}

// ---------------------------------------------------------------------------
// scratch (static device arrays; allocations are forbidden)
// ---------------------------------------------------------------------------
__device__ float  g_S  [BATCH * HW * HW];                    // 67 MB
__device__ __half g_xnT[BATCH * HW * C_DIM];
__device__ __half g_q  [BATCH * HW * C_DIM];
__device__ __half g_k  [BATCH * HW * C_DIM];
__device__ __half g_v  [BATCH * C_DIM * HW];
__device__ __half g_at [BATCH * HW * HW];
__device__ __half g_h  [BATCH * HW * C_DIM];
__device__ __half g_wq [3 * C_DIM * C_DIM];
__device__ __half g_wp [C_DIM * C_DIM];

// ---------------------------------------------------------------------------
// Fused GroupNorm + transpose + fp16 convert: x [C,HW] -> xnT [HW,C]
// one block per (b, g); group region contiguous (16 ch x 1024)
// ---------------------------------------------------------------------------
__global__ __launch_bounds__(256) void gn_transpose_cvt(
    const float* __restrict__ x, const float* __restrict__ w,
    const float* __restrict__ b, __half* __restrict__ th)
{
    const int bg = blockIdx.x;
    const int bz = bg >> 5, g = bg & 31;
    const float* xp = x + (size_t)bg * GROUP_ELEMS;
    const int tid = threadIdx.x;

    float s = 0.f, ss = 0.f;
    for (int i = tid; i < GROUP_ELEMS; i += 256) {
        float v = xp[i]; s += v; ss += v * v;
    }
    __shared__ float r0[256], r1[256];
    r0[tid] = s; r1[tid] = ss;
    __syncthreads();
    for (int st = 128; st > 0; st >>= 1) {
        if (tid < st) { r0[tid] += r0[tid + st]; r1[tid] += r1[tid + st]; }
        __syncthreads();
    }
    const float mean = r0[0] * (1.0f / GROUP_ELEMS);
    const float var  = r1[0] * (1.0f / GROUP_ELEMS) - mean * mean;
    const float inv  = rsqrtf(var + 1e-5f);

    __shared__ float t[CPG][257];
    __shared__ float sca[CPG], shf[CPG];
    if (tid < CPG) {
        float a = w[g * CPG + tid] * inv;
        sca[tid] = a;
        shf[tid] = b[g * CPG + tid] - mean * a;
    }
    __syncthreads();

    __half* oh = th + (size_t)bz * (HW * C_DIM) + g * CPG;

    for (int wb = 0; wb < 4; wb++) {
#pragma unroll
        for (int r = 0; r < CPG; r++)
            t[r][tid] = xp[r * HW + wb * 256 + tid];
        __syncthreads();
        __align__(16) __half hh[CPG];
#pragma unroll
        for (int c = 0; c < CPG; c++)
            hh[c] = __float2half(t[c][tid] * sca[c] + shf[c]);
        const size_t o = (size_t)(wb * 256 + tid) * C_DIM;
        *reinterpret_cast<uint4*>(oh + o)     = *reinterpret_cast<const uint4*>(hh);
        *reinterpret_cast<uint4*>(oh + o + 8) = *reinterpret_cast<const uint4*>(hh + 8);
        __syncthreads();
    }
}

// elementwise fp32 -> fp16 (weights)
__global__ __launch_bounds__(256) void cvt_half(
    const float* __restrict__ s, __half* __restrict__ h, int n)
{
    int i = blockIdx.x * 256 + threadIdx.x;
    if (i < n) h[i] = __float2half(s[i]);
}

// ---------------------------------------------------------------------------
// softmax over 1024 + fp16 convert
// ---------------------------------------------------------------------------
__global__ __launch_bounds__(256) void softmax_cvt(
    const float* __restrict__ S, __half* __restrict__ ah)
{
    const size_t roff = (size_t)blockIdx.x * HW;
    const int tid = threadIdx.x;
    float4 v = reinterpret_cast<const float4*>(S + roff)[tid];
    __shared__ float red[256];
    float m = fmaxf(fmaxf(v.x, v.y), fmaxf(v.z, v.w));
    red[tid] = m; __syncthreads();
    for (int st = 128; st > 0; st >>= 1) {
        if (tid < st) red[tid] = fmaxf(red[tid], red[tid + st]);
        __syncthreads();
    }
    m = red[0]; __syncthreads();
    v.x = __expf(v.x - m); v.y = __expf(v.y - m);
    v.z = __expf(v.z - m); v.w = __expf(v.w - m);
    red[tid] = v.x + v.y + v.z + v.w; __syncthreads();
    for (int st = 128; st > 0; st >>= 1) {
        if (tid < st) red[tid] += red[tid + st];
        __syncthreads();
    }
    const float inv = 1.0f / red[0];
    __align__(8) __half h4[4];
    h4[0] = __float2half(v.x * inv);
    h4[1] = __float2half(v.y * inv);
    h4[2] = __float2half(v.z * inv);
    h4[3] = __float2half(v.w * inv);
    *reinterpret_cast<uint2*>(ah + roff + tid * 4) = *reinterpret_cast<const uint2*>(h4);
}

// ---------------------------------------------------------------------------
// HMMA fp16 GEMM: D[i,j] = sum_k A[i,k]*B[j,k]  (A:[M,K] ldA, B:[N,K] ldB)
// CTA 128x128, K-chunk 64, 256 thr, 3-stage cp.async pipeline (2 tiles/stage).
// MODE 0: QKV epilogue (bias; q scaled [n,512], k [n,512], v transposed [c,n])
// MODE 1: plain fp32 out (S)
// MODE 2: fp16 out, ld 512 (h)
// MODE 3: proj: transpose store + bias + residual -> out [o, n] fp32
// ---------------------------------------------------------------------------
#define STAGE_BYTES 32768                 // 2 tiles x 16KB
#define NSTAGE      3
#define GEMM_SMEM   (NSTAGE * STAGE_BYTES)   // 96KB (also covers epilogue smf 66KB)

__device__ __forceinline__ void load_tile_async(
    const __half* __restrict__ g, int ld, uint32_t sbase, int tid)
{
#pragma unroll
    for (int r = 0; r < 4; r++) {
        int idx = r * 256 + tid;
        int row = idx >> 3, c = idx & 7;
        uint32_t off = (uint32_t)(row * 128) + (uint32_t)((c ^ (row & 7)) << 4);
        cp16(sbase + off, g + (size_t)row * ld + c * 8);
    }
}

template<int MODE>
__global__ void __launch_bounds__(256) hmma_gemm(
    const __half* __restrict__ Ah, long bsA, int ldA,
    const __half* __restrict__ B_, long bsB, int ldB,
    int K, int ldD, long bsD,
    float* __restrict__ po0, __half* __restrict__ po1,
    __half* __restrict__ po3, __half* __restrict__ po4,
    const float* __restrict__ bias, const float* __restrict__ res, long bsR,
    float qscale)
{
    extern __shared__ char smem[];
    const uint32_t sb = smem_u32(smem);
    const int tid = threadIdx.x, wid = tid >> 5, lane = tid & 31;
    const int wm = wid >> 2, wn = wid & 3;          // warps 2(M) x 4(N)
    const int bz = blockIdx.z;
    const int m0 = blockIdx.y << 7, j0 = blockIdx.x << 7;

    const __half* a_p = Ah + (size_t)bz * bsA + (size_t)m0 * ldA;
    const __half* b_p = B_ + (size_t)bz * bsB + (size_t)j0 * ldB;

    const int NC = K >> 6;

    // prologue: stages 0, 1
    load_tile_async(a_p,      ldA, sb + 0,                   tid);
    load_tile_async(b_p,      ldB, sb + 16384,               tid);
    CP_COMMIT();
    load_tile_async(a_p + 64, ldA, sb + STAGE_BYTES + 0,     tid);
    load_tile_async(b_p + 64, ldB, sb + STAGE_BYTES + 16384, tid);
    CP_COMMIT();

    float acc[4][4][4];
#pragma unroll
    for (int i = 0; i < 4; i++)
#pragma unroll
        for (int j = 0; j < 4; j++)
#pragma unroll
            for (int t = 0; t < 4; t++) acc[i][j][t] = 0.f;

    const int lr = lane & 15, lc = lane >> 4;

    for (int ch = 0; ch < NC; ch++) {
        if (ch <= NC - 2) {
            asm volatile("cp.async.wait_group 1;" ::: "memory");
        } else {
            asm volatile("cp.async.wait_group 0;" ::: "memory");
        }
        __syncthreads();

        if (ch + 2 < NC) {
            const uint32_t nsb = sb + (uint32_t)(((ch + 2) % NSTAGE) * STAGE_BYTES);
            const size_t ko = (size_t)(ch + 2) << 6;
            load_tile_async(a_p + ko, ldA, nsb + 0,     tid);
            load_tile_async(b_p + ko, ldB, nsb + 16384, tid);
            CP_COMMIT();
        }

        const uint32_t sa = sb + (uint32_t)((ch % NSTAGE) * STAGE_BYTES);
#pragma unroll
        for (int ks = 0; ks < 4; ks++) {
            uint32_t ah[4][4], bh[4][2];
            const int c = ks * 2 + lc;
#pragma unroll
            for (int mt = 0; mt < 4; mt++) {
                const int row = wm * 64 + mt * 16 + lr;
                const uint32_t addr = sa + (uint32_t)(row * 128)
                                    + (uint32_t)(((c ^ (row & 7)) << 4));
                ldmatrix_x4(ah[mt], addr);
            }
#pragma unroll
            for (int bt = 0; bt < 2; bt++) {
                const int row = wn * 32 + bt * 16 + lr;
                const uint32_t addr = sa + 16384 + (uint32_t)(row * 128)
                                    + (uint32_t)(((c ^ (row & 7)) << 4));
                uint32_t t0[4];
                ldmatrix_x4(t0, addr);
                bh[bt * 2][0] = t0[0]; bh[bt * 2][1] = t0[2];
                bh[bt * 2 + 1][0] = t0[1]; bh[bt * 2 + 1][1] = t0[3];
            }
#pragma unroll
            for (int mt = 0; mt < 4; mt++)
#pragma unroll
                for (int nt = 0; nt < 4; nt++)
                    mma_f16(acc[mt][nt], ah[mt], bh[nt]);
        }
    }
    __syncthreads();

    // ------------------------- epilogue -------------------------
    const int g  = lane >> 2;
    const int tg = lane & 3;

    if ((MODE == 0 && j0 >= 1024) || MODE == 3) {
        // stage fp32 tile transposed in smem: smf[col_local][row_local]
        float* smf = reinterpret_cast<float*>(smem);
#pragma unroll
        for (int mt = 0; mt < 4; mt++)
#pragma unroll
            for (int nt = 0; nt < 4; nt++) {
                const int rl = wm * 64 + mt * 16 + g;
                const int cl = wn * 32 + nt * 8 + 2 * tg;
                smf[(cl)     * 129 + rl]     = acc[mt][nt][0];
                smf[(cl + 1) * 129 + rl]     = acc[mt][nt][1];
                smf[(cl)     * 129 + rl + 8] = acc[mt][nt][2];
                smf[(cl + 1) * 129 + rl + 8] = acc[mt][nt][3];
            }
        __syncthreads();

        if (MODE == 0) {
            // v: out[c, n] fp16, c = j0-1024+cl, n = m0+nl
            const size_t vb = (size_t)bz * ((size_t)C_DIM * HW);
#pragma unroll 4
            for (int i = 0; i < 32; i++) {
                const int idx = tid + i * 256;
                const int cl = idx >> 6, nl = (idx & 63) * 2;
                const float bv = bias[j0 + cl];
                float v0 = smf[cl * 129 + nl]     + bv;
                float v1 = smf[cl * 129 + nl + 1] + bv;
                const size_t o = vb + (size_t)(j0 - 1024 + cl) * HW + m0 + nl;
                *reinterpret_cast<uint32_t*>(po4 + o) =
                    pack2h(__float2half(v0), __float2half(v1));
            }
        } else {
            // proj: out[o, n] = D[n, o] + bias[o] + x[o, n]
            float* op = po0 + (size_t)bz * bsD;
            const float* rp = res + (size_t)bz * bsR;
#pragma unroll 4
            for (int i = 0; i < 16; i++) {
                const int idx = tid + i * 256;
                const int ol = idx >> 5, nl = (idx & 31) * 4;
                const float bv = bias[j0 + ol];
                const size_t o = (size_t)(j0 + ol) * HW + m0 + nl;
                float4 rv = *reinterpret_cast<const float4*>(rp + o);
                float4 vv;
                vv.x = smf[ol * 129 + nl]     + bv + rv.x;
                vv.y = smf[ol * 129 + nl + 1] + bv + rv.y;
                vv.z = smf[ol * 129 + nl + 2] + bv + rv.z;
                vv.w = smf[ol * 129 + nl + 3] + bv + rv.w;
                *reinterpret_cast<float4*>(op + o) = vv;
            }
        }
        return;
    }

#pragma unroll
    for (int mt = 0; mt < 4; mt++) {
#pragma unroll
        for (int nt = 0; nt < 4; nt++) {
            const int r0  = m0 + wm * 64 + mt * 16 + g;
            const int col = j0 + wn * 32 + nt * 8 + 2 * tg;
            float v0 = acc[mt][nt][0], v1 = acc[mt][nt][1];
            float v2 = acc[mt][nt][2], v3 = acc[mt][nt][3];

            if (MODE == 0) {
                const float b0 = bias[col], b1 = bias[col + 1];
                v0 += b0; v1 += b1; v2 += b0; v3 += b1;
            }

            if (MODE == 1) {
                float* op = po0 + (size_t)bz * bsD;
                *reinterpret_cast<float2*>(op + (size_t)r0 * ldD + col)       = make_float2(v0, v1);
                *reinterpret_cast<float2*>(op + (size_t)(r0 + 8) * ldD + col) = make_float2(v2, v3);
            } else if (MODE == 0 && col >= 512) {
                // k: fp16 [n, 512]
                const size_t o0 = (size_t)bz * bsD + (size_t)r0 * 512 + (col - 512);
                const size_t o1 = (size_t)bz * bsD + (size_t)(r0 + 8) * 512 + (col - 512);
                *reinterpret_cast<uint32_t*>(po3 + o0) = pack2h(__float2half(v0), __float2half(v1));
                *reinterpret_cast<uint32_t*>(po3 + o1) = pack2h(__float2half(v2), __float2half(v3));
            } else {
                // MODE 0 q (scaled) / MODE 2 h: fp16, ld 512
                if (MODE == 0) { v0 *= qscale; v1 *= qscale; v2 *= qscale; v3 *= qscale; }
                const size_t o0 = (size_t)bz * bsD + (size_t)r0 * 512 + col;
                const size_t o1 = (size_t)bz * bsD + (size_t)(r0 + 8) * 512 + col;
                *reinterpret_cast<uint32_t*>(po1 + o0) = pack2h(__float2half(v0), __float2half(v1));
                *reinterpret_cast<uint32_t*>(po1 + o1) = pack2h(__float2half(v2), __float2half(v3));
            }
        }
    }
}

// ---------------------------------------------------------------------------
extern "C" void kernel_launch(void* const* d_in, const int* in_sizes, int n_in,
                              void* d_out, int out_size)
{
    const float* x      = (const float*)d_in[0];
    const float* norm_w = (const float*)d_in[1];
    const float* norm_b = (const float*)d_in[2];
    const float* qkv_w  = (const float*)d_in[3];
    const float* qkv_b  = (const float*)d_in[4];
    const float* proj_w = (const float*)d_in[5];
    const float* proj_b = (const float*)d_in[6];
    float* out = (float*)d_out;

    float *S;
    __half *xnT, *q_, *k_, *v_, *at, *h_, *wq, *wp;
    cudaGetSymbolAddress((void**)&S,   g_S);
    cudaGetSymbolAddress((void**)&xnT, g_xnT);
    cudaGetSymbolAddress((void**)&q_,  g_q);
    cudaGetSymbolAddress((void**)&k_,  g_k);
    cudaGetSymbolAddress((void**)&v_,  g_v);
    cudaGetSymbolAddress((void**)&at,  g_at);
    cudaGetSymbolAddress((void**)&h_,  g_h);
    cudaGetSymbolAddress((void**)&wq,  g_wq);
    cudaGetSymbolAddress((void**)&wp,  g_wp);

    cudaFuncSetAttribute(hmma_gemm<0>, cudaFuncAttributeMaxDynamicSharedMemorySize, GEMM_SMEM);
    cudaFuncSetAttribute(hmma_gemm<1>, cudaFuncAttributeMaxDynamicSharedMemorySize, GEMM_SMEM);
    cudaFuncSetAttribute(hmma_gemm<2>, cudaFuncAttributeMaxDynamicSharedMemorySize, GEMM_SMEM);
    cudaFuncSetAttribute(hmma_gemm<3>, cudaFuncAttributeMaxDynamicSharedMemorySize, GEMM_SMEM);

    const long nCHW = (long)C_DIM * HW;   // 524288
    const long nSS  = (long)HW * HW;      // 1048576
    const float qscale = 0.04419417382415922f;  // 1/sqrt(512)

    // 1) fused GroupNorm + transpose + fp16 -> xnT [HW, C]
    gn_transpose_cvt<<<BATCH * GROUPS, 256>>>(x, norm_w, norm_b, xnT);

    // 2) weight conversions (fp16)
    cvt_half<<<(3 * C_DIM * C_DIM + 255) / 256, 256>>>(qkv_w, wq, 3 * C_DIM * C_DIM);
    cvt_half<<<(C_DIM * C_DIM + 255) / 256, 256>>>(proj_w, wp, C_DIM * C_DIM);

    // 3) QKV: D[n,o] = xnT[n,:] . W[o,:] + b[o];  q scaled, k, v transposed
    hmma_gemm<0><<<dim3(12, 8, BATCH), 256, GEMM_SMEM>>>(
        xnT, nCHW, C_DIM,
        wq, 0, C_DIM,
        C_DIM, 512, nCHW,
        nullptr, q_, k_, v_, qkv_b, nullptr, 0, qscale);

    // 4) S[n,m] = q[n,:] . k[m,:]   (q pre-scaled)
    hmma_gemm<1><<<dim3(8, 8, BATCH), 256, GEMM_SMEM>>>(
        q_, nCHW, C_DIM,
        k_, nCHW, C_DIM,
        C_DIM, HW, nSS,
        S, nullptr, nullptr, nullptr, nullptr, nullptr, 0, 1.0f);

    // 5) softmax + fp16 convert
    softmax_cvt<<<BATCH * HW, 256>>>(S, at);

    // 6) h[n,c] = attn[n,:] . v[c,:]   (v stored [c, m])
    hmma_gemm<2><<<dim3(4, 8, BATCH), 256, GEMM_SMEM>>>(
        at, nSS, HW,
        v_, nCHW, HW,
        HW, 512, nCHW,
        nullptr, h_, nullptr, nullptr, nullptr, nullptr, 0, 1.0f);

    // 7) proj: D[n,o] = h[n,:] . wp[o,:]; out[o,n] = D + proj_b[o] + x[o,n]
    hmma_gemm<3><<<dim3(4, 8, BATCH), 256, GEMM_SMEM>>>(
        h_, nCHW, C_DIM,
        wp, 0, C_DIM,
        C_DIM, HW, nCHW,
        out, nullptr, nullptr, nullptr, proj_b, x, nCHW, 1.0f);

    (void)in_sizes; (void)n_in; (void)out_size;
}